// round 4
// baseline (speedup 1.0000x reference)
#include <cuda_runtime.h>
#include <cstdint>

#define NB 16
#define NT 2048
#define ND 512
#define NH 512
#define G3 1536   // 3H
#define KD 1024   // 2D (history tap + current tap)

#define BM 128
#define BN 128
#define BK 16
#define TM 8
#define TN 8

#define NC 8            // scan chunks
#define CT (NT / NC)    // 256 timesteps per chunk

// Scratch (allocation-free rule: __device__ globals)
__device__ float g_W[(size_t)KD * G3];                 // ~6 MB, [kk][n]
__device__ float g_gates[(size_t)NB * NT * G3];        // ~201 MB post-activation gates
__device__ float g_carryA[(size_t)NB * NC * NH];       // per-chunk A = prod f
__device__ float g_carryB[(size_t)NB * NC * NH];       // per-chunk B
__device__ float g_cin[(size_t)NB * NC * NH];          // chunk entry state

// ---------------------------------------------------------------------------
// Repack conv_w [3H, D, K=2] -> g_W [2D, 3H]; rows 0..511 = k=0 (history),
// rows 512..1023 = k=1 (current). Coalesced writes.
// ---------------------------------------------------------------------------
__global__ void transpose_w_kernel(const float* __restrict__ w) {
    int idx = blockIdx.x * blockDim.x + threadIdx.x;
    if (idx >= KD * G3) return;
    int kk = idx / G3;
    int n  = idx - kk * G3;
    int d  = kk & (ND - 1);
    int ki = kk >> 9;                       // 0 = history tap, 1 = current tap
    g_W[idx] = w[(size_t)n * (ND * 2) + d * 2 + ki];
}

// ---------------------------------------------------------------------------
// gates = A @ W + b, fused tanh/sigmoid epilogue.
// A[m][kk] = x[m*512 + kk - 512], zeroed when (kk<512 && t==0). t = m & 2047.
// ---------------------------------------------------------------------------
__global__ __launch_bounds__(256, 2)
void gemm_gates_kernel(const float* __restrict__ x,
                       const float* __restrict__ bias) {
    __shared__ float As[BK][BM];
    __shared__ float Bs[BK][BN];

    const int m0  = blockIdx.y * BM;
    const int n0  = blockIdx.x * BN;
    const int tid = threadIdx.x;
    const int tx  = tid & 15;               // 0..15 -> 8 cols each
    const int ty  = tid >> 4;               // 0..15 -> 8 rows each

    // A-load mapping: float4 along kk
    const int arow = tid >> 2;              // 0..63 (+64 for second half)
    const int ac4  = (tid & 3) * 4;         // 0,4,8,12
    // B-load mapping: float4 along n
    const int brow = tid >> 5;              // 0..7 (+8)
    const int bc4  = (tid & 31) * 4;        // 0..124

    float acc[TM][TN];
#pragma unroll
    for (int i = 0; i < TM; i++)
#pragma unroll
        for (int j = 0; j < TN; j++) acc[i][j] = 0.f;

    for (int k0 = 0; k0 < KD; k0 += BK) {
        const bool hist = (k0 < ND);        // whole K-tile is one tap (512 % 16 == 0)

        // Load A tile (128 x 16), store transposed As[kk][m]
#pragma unroll
        for (int r = 0; r < 2; r++) {
            const int row = arow + r * 64;
            const int m   = m0 + row;
            const int t   = m & (NT - 1);
            float4 v;
            if (hist && t == 0) {
                v = make_float4(0.f, 0.f, 0.f, 0.f);
            } else {
                v = *reinterpret_cast<const float4*>(
                        x + (size_t)m * ND + (k0 + ac4) - ND);
            }
            As[ac4 + 0][row] = v.x;
            As[ac4 + 1][row] = v.y;
            As[ac4 + 2][row] = v.z;
            As[ac4 + 3][row] = v.w;
        }
        // Load B tile (16 x 128)
#pragma unroll
        for (int r = 0; r < 2; r++) {
            const int kt = brow + r * 8;
            *reinterpret_cast<float4*>(&Bs[kt][bc4]) =
                *reinterpret_cast<const float4*>(
                    &g_W[(size_t)(k0 + kt) * G3 + n0 + bc4]);
        }
        __syncthreads();

#pragma unroll
        for (int kt = 0; kt < BK; kt++) {
            float af[TM], bf[TN];
            *reinterpret_cast<float4*>(&af[0]) =
                *reinterpret_cast<const float4*>(&As[kt][ty * TM]);
            *reinterpret_cast<float4*>(&af[4]) =
                *reinterpret_cast<const float4*>(&As[kt][ty * TM + 4]);
            *reinterpret_cast<float4*>(&bf[0]) =
                *reinterpret_cast<const float4*>(&Bs[kt][tx * TN]);
            *reinterpret_cast<float4*>(&bf[4]) =
                *reinterpret_cast<const float4*>(&Bs[kt][tx * TN + 4]);
#pragma unroll
            for (int i = 0; i < TM; i++)
#pragma unroll
                for (int j = 0; j < TN; j++)
                    acc[i][j] = fmaf(af[i], bf[j], acc[i][j]);
        }
        __syncthreads();
    }

    // Epilogue: + bias, tanh for Z (n<512), sigmoid for F/O. Column tile is
    // 128-aligned and 512 % 128 == 0, so the activation branch is CTA-uniform.
    float bs[TN];
#pragma unroll
    for (int j = 0; j < TN; j++) bs[j] = bias[n0 + tx * TN + j];

#pragma unroll
    for (int i = 0; i < TM; i++) {
        const int m = m0 + ty * TM + i;
        float vo[TN];
#pragma unroll
        for (int j = 0; j < TN; j++) {
            const int n = n0 + tx * TN + j;
            const float v = acc[i][j] + bs[j];
            vo[j] = (n < NH) ? tanhf(v) : (1.f / (1.f + __expf(-v)));
        }
        float* dst = &g_gates[(size_t)m * G3 + n0 + tx * TN];
        *reinterpret_cast<float4*>(dst)     = make_float4(vo[0], vo[1], vo[2], vo[3]);
        *reinterpret_cast<float4*>(dst + 4) = make_float4(vo[4], vo[5], vo[6], vo[7]);
    }
}

// ---------------------------------------------------------------------------
// fo-pool as a chunked linear-recurrence scan.
// c_t = f*c_{t-1} + (1-f)*z_t composes: over a chunk, c_out = A*c_in + B with
// A = prod f, B = recurrence started from 0.
// Pass 1: per-(b,chunk,h) compute (A, B).            65536 threads.
// Pass 2: per-(b,h) scan the NC chunk carries.        8192 threads (tiny).
// Pass 3: per-(b,chunk,h) recompute from c_in, write C and O*C.
// Thread mapping keeps h in the low bits -> fully coalesced gate reads.
// ---------------------------------------------------------------------------
__global__ __launch_bounds__(256)
void fo_carry_kernel() {
    const int idx   = blockIdx.x * blockDim.x + threadIdx.x;  // 0..65535
    const int h     = idx & (NH - 1);
    const int chunk = (idx >> 9) & (NC - 1);
    const int b     = idx >> 12;

    const float* g = g_gates + ((size_t)b * NT + (size_t)chunk * CT) * G3 + h;
    float A = 1.f, Bc = 0.f;
#pragma unroll 4
    for (int t = 0; t < CT; t++) {
        const float* gt = g + (size_t)t * G3;
        const float z = gt[0];
        const float f = gt[NH];
        Bc = f * Bc + (1.f - f) * z;
        A *= f;
    }
    const size_t ci = ((size_t)b * NC + chunk) * NH + h;
    g_carryA[ci] = A;
    g_carryB[ci] = Bc;
}

__global__ __launch_bounds__(256)
void fo_carry_scan_kernel() {
    const int idx = blockIdx.x * blockDim.x + threadIdx.x;    // 0..8191
    const int h = idx & (NH - 1);
    const int b = idx >> 9;
    float c = 0.f;
#pragma unroll
    for (int j = 0; j < NC; j++) {
        const size_t ci = ((size_t)b * NC + j) * NH + h;
        g_cin[ci] = c;
        c = g_carryA[ci] * c + g_carryB[ci];
    }
}

__global__ __launch_bounds__(256)
void fo_apply_kernel(float* __restrict__ out) {
    const int idx   = blockIdx.x * blockDim.x + threadIdx.x;  // 0..65535
    const int h     = idx & (NH - 1);
    const int chunk = (idx >> 9) & (NC - 1);
    const int b     = idx >> 12;

    const float* g = g_gates + ((size_t)b * NT + (size_t)chunk * CT) * G3 + h;
    float* Cp  = out + ((size_t)b * NT + (size_t)chunk * CT) * NH + h;
    float* OCp = Cp + (size_t)NB * NT * NH;

    float c = g_cin[((size_t)b * NC + chunk) * NH + h];
#pragma unroll 4
    for (int t = 0; t < CT; t++) {
        const float* gt = g + (size_t)t * G3;
        const float z = gt[0];
        const float f = gt[NH];
        const float o = gt[2 * NH];
        c = f * c + (1.f - f) * z;
        Cp[(size_t)t * NH]  = c;
        OCp[(size_t)t * NH] = o * c;
    }
}

// ---------------------------------------------------------------------------
extern "C" void kernel_launch(void* const* d_in, const int* in_sizes, int n_in,
                              void* d_out, int out_size) {
    const float* x    = (const float*)d_in[0];   // [B, T, D]
    const float* w    = (const float*)d_in[1];   // [3H, D, 2]
    const float* bias = (const float*)d_in[2];   // [3H]
    float* out = (float*)d_out;                  // [2, B, T, H] (C then O*C)

    transpose_w_kernel<<<(KD * G3 + 255) / 256, 256>>>(w);

    dim3 grid(G3 / BN, (NB * NT) / BM);          // (12, 256)
    gemm_gates_kernel<<<grid, 256>>>(x, bias);

    fo_carry_kernel<<<(NB * NC * NH) / 256, 256>>>();
    fo_carry_scan_kernel<<<(NB * NH) / 256, 256>>>();
    fo_apply_kernel<<<(NB * NC * NH) / 256, 256>>>(out);
}

// round 7
// speedup vs baseline: 3.0137x; 3.0137x over previous
#include <cuda_runtime.h>
#include <cstdint>

#define NB 16
#define NT 2048
#define ND 512
#define NH 512
#define G3 1536
#define KD 1024

#define BM 128
#define BN 128
#define BK 16
#define KITER (KD / BK)      // 64
#define NSTAGE 4

// smem pitches (floats) chosen for conflict-free mma fragment loads
#define PKA 20               // A row-major [BM][PKA]
#define PNB 136              // B k-major  [BK][PNB]
#define A_EL (BM * PKA)      // 2560 floats / stage
#define B_EL (BK * PNB)      // 2176 floats / stage
#define A_BYTES (A_EL * 4)   // 10240
#define B_BYTES (B_EL * 4)   // 8704
#define B_OFF   (NSTAGE * A_BYTES)               // 40960
#define SMEM_TOTAL (NSTAGE * (A_BYTES + B_BYTES))// 75776

#define NC 8
#define CT (NT / NC)

// Scratch (__device__ globals; no allocation allowed)
__device__ float g_xp[(size_t)NB * (NT + 1) * ND];   // tf32-rounded, zero-padded x
__device__ float g_Wk[(size_t)KD * G3];              // tf32-rounded W, [kk][n]
__device__ float g_gates[(size_t)NB * NT * G3];      // post-activation gates
__device__ float g_carryA[(size_t)NB * NC * NH];
__device__ float g_carryB[(size_t)NB * NC * NH];
__device__ float g_cin[(size_t)NB * NC * NH];

// ---------------------------------------------------------------------------
__device__ __forceinline__ uint32_t s2u(const void* p) {
    uint32_t a;
    asm("{ .reg .u64 t; cvta.to.shared.u64 t, %1; cvt.u32.u64 %0, t; }"
        : "=r"(a) : "l"(p));
    return a;
}
__device__ __forceinline__ void cp16(uint32_t dst, const void* src) {
    asm volatile("cp.async.cg.shared.global [%0], [%1], 16;" :: "r"(dst), "l"(src));
}
__device__ __forceinline__ float tf32r(float v) {
    uint32_t o;
    asm("cvt.rna.tf32.f32 %0, %1;" : "=r"(o) : "f"(v));
    return __uint_as_float(o);
}
__device__ __forceinline__ void mma_tf32(float* c, const uint32_t* a,
                                         const uint32_t* b) {
    asm volatile(
        "mma.sync.aligned.m16n8k8.row.col.f32.tf32.tf32.f32 "
        "{%0,%1,%2,%3}, {%4,%5,%6,%7}, {%8,%9}, {%0,%1,%2,%3};"
        : "+f"(c[0]), "+f"(c[1]), "+f"(c[2]), "+f"(c[3])
        : "r"(a[0]), "r"(a[1]), "r"(a[2]), "r"(a[3]), "r"(b[0]), "r"(b[1]));
}

// ---------------------------------------------------------------------------
// Prep: g_xp[b][0]=0, g_xp[b][tt]=tf32(x[b][tt-1]); both conv taps become unit
// row shifts of one buffer. W repacked k-major: g_Wk[ki*512+d][n]=tf32(w[n,d,ki]).
// ---------------------------------------------------------------------------
__global__ void pad_x_kernel(const float4* __restrict__ x) {
    const int PB = (NT + 1) * ND / 4;
    int idx = blockIdx.x * blockDim.x + threadIdx.x;
    if (idx >= NB * PB) return;
    int b = idx / PB;
    int r = idx - b * PB;
    float4 v = make_float4(0.f, 0.f, 0.f, 0.f);
    if (r >= ND / 4) {
        v = x[(size_t)b * (NT * ND / 4) + r - ND / 4];
        v.x = tf32r(v.x); v.y = tf32r(v.y); v.z = tf32r(v.z); v.w = tf32r(v.w);
    }
    reinterpret_cast<float4*>(g_xp)[idx] = v;
}

__global__ void transpose_wk_kernel(const float* __restrict__ w) {
    int idx = blockIdx.x * blockDim.x + threadIdx.x;   // [kk][n]
    if (idx >= KD * G3) return;
    int kk = idx / G3;
    int n  = idx - kk * G3;
    int ki = kk >> 9, d = kk & 511;
    g_Wk[idx] = tf32r(w[(size_t)n * KD + d * 2 + ki]);
}

// ---------------------------------------------------------------------------
// tf32 mma.sync GEMM: gates = act(A @ W + bias).
// A row m=(b,t): [xp[b][t][:] | xp[b][t+1][:]]. 4-stage cp.async pipeline.
// 8 warps: 2(M) x 4(N), warp tile 64x32, mma m16n8k8.
// ---------------------------------------------------------------------------
__global__ __launch_bounds__(256, 2)
void gemm_mma_kernel(const float* __restrict__ bias) {
    extern __shared__ float sm[];
    const uint32_t sb = s2u(sm);
    const int tid = threadIdx.x;
    const int wid = tid >> 5, lid = tid & 31;
    const int wm = wid & 1, wn = wid >> 1;
    const int g = lid >> 2, tig = lid & 3;

    const int n0 = blockIdx.x * BN;
    const int m0 = blockIdx.y * BM;
    const int b  = m0 >> 11;
    const int t0 = m0 & (NT - 1);

    float cf[4][4][4];
#pragma unroll
    for (int i = 0; i < 4; i++)
#pragma unroll
        for (int j = 0; j < 4; j++)
#pragma unroll
            for (int q = 0; q < 4; q++) cf[i][j][q] = 0.f;

    auto load_chunk = [&](int c, int s) {
        const int k0  = c * BK;
        const int tap = (k0 >= ND) ? 1 : 0;
        const int d0  = k0 & (ND - 1);
        const float* asrc = g_xp + ((size_t)(b * (NT + 1) + t0 + tap)) * ND + d0;
        const uint32_t adst = sb + s * A_BYTES;
#pragma unroll
        for (int i = 0; i < 2; i++) {
            int idx = tid + (i << 8);                // 0..511
            int r = idx >> 2, cc = (idx & 3) << 2;
            cp16(adst + (r * PKA + cc) * 4, asrc + (size_t)r * ND + cc);
        }
        const float* bsrc = g_Wk + (size_t)k0 * G3 + n0;
        const uint32_t bdst = sb + B_OFF + s * B_BYTES;
#pragma unroll
        for (int i = 0; i < 2; i++) {
            int idx = tid + (i << 8);
            int r = idx >> 5, cc = (idx & 31) << 2;
            cp16(bdst + (r * PNB + cc) * 4, bsrc + (size_t)r * G3 + cc);
        }
    };

    // Prologue: fill 3 stages
#pragma unroll
    for (int c = 0; c < NSTAGE - 1; c++) {
        load_chunk(c, c);
        asm volatile("cp.async.commit_group;");
    }

    for (int c = 0; c < KITER; c++) {
        const int s = c & (NSTAGE - 1);
        asm volatile("cp.async.wait_group %0;" :: "n"(NSTAGE - 2));
        __syncthreads();

        const int cn = c + NSTAGE - 1;
        if (cn < KITER) load_chunk(cn, cn & (NSTAGE - 1));
        asm volatile("cp.async.commit_group;");

        const uint32_t* As = reinterpret_cast<const uint32_t*>(sm) + s * A_EL;
        const uint32_t* Bs = reinterpret_cast<const uint32_t*>(sm) +
                             (B_OFF >> 2) + s * B_EL;
#pragma unroll
        for (int k8 = 0; k8 < 2; k8++) {
            const int kk = k8 * 8;
            uint32_t af[4][4], bf[4][2];
#pragma unroll
            for (int i = 0; i < 4; i++) {
                const int base = (wm * 64 + i * 16 + g) * PKA + kk + tig;
                af[i][0] = As[base];
                af[i][1] = As[base + 8 * PKA];
                af[i][2] = As[base + 4];
                af[i][3] = As[base + 8 * PKA + 4];
            }
#pragma unroll
            for (int j = 0; j < 4; j++) {
                const int base = (kk + tig) * PNB + wn * 32 + j * 8 + g;
                bf[j][0] = Bs[base];
                bf[j][1] = Bs[base + 4 * PNB];
            }
#pragma unroll
            for (int i = 0; i < 4; i++)
#pragma unroll
                for (int j = 0; j < 4; j++) mma_tf32(cf[i][j], af[i], bf[j]);
        }
    }

    // Epilogue: bias + activation, direct store to g_gates.
    // c0,c1 -> (row g, cols 2tig,2tig+1); c2,c3 -> row g+8.
#pragma unroll
    for (int j = 0; j < 4; j++) {
        const int col = n0 + wn * 32 + j * 8 + 2 * tig;
        const float b0 = bias[col], b1 = bias[col + 1];
        const bool is_z = col < NH;
#pragma unroll
        for (int i = 0; i < 4; i++) {
            const int r0 = m0 + wm * 64 + i * 16 + g;
#pragma unroll
            for (int h = 0; h < 2; h++) {
                float v0 = cf[i][j][2 * h]     + b0;
                float v1 = cf[i][j][2 * h + 1] + b1;
                float o0, o1;
                if (is_z) {
                    float e0 = __expf(2.f * v0), e1 = __expf(2.f * v1);
                    o0 = 1.f - __fdividef(2.f, e0 + 1.f);
                    o1 = 1.f - __fdividef(2.f, e1 + 1.f);
                } else {
                    o0 = __fdividef(1.f, 1.f + __expf(-v0));
                    o1 = __fdividef(1.f, 1.f + __expf(-v1));
                }
                *reinterpret_cast<float2*>(
                    g_gates + (size_t)(r0 + 8 * h) * G3 + col) =
                    make_float2(o0, o1);
            }
        }
    }
}

// ---------------------------------------------------------------------------
// fo-pool: chunked linear-recurrence scan (unchanged, passing since R4)
// ---------------------------------------------------------------------------
__global__ __launch_bounds__(256)
void fo_carry_kernel() {
    const int idx   = blockIdx.x * blockDim.x + threadIdx.x;
    const int h     = idx & (NH - 1);
    const int chunk = (idx >> 9) & (NC - 1);
    const int b     = idx >> 12;

    const float* gp = g_gates + ((size_t)b * NT + (size_t)chunk * CT) * G3 + h;
    float A = 1.f, Bc = 0.f;
#pragma unroll 4
    for (int t = 0; t < CT; t++) {
        const float* gt = gp + (size_t)t * G3;
        const float z = gt[0];
        const float f = gt[NH];
        Bc = f * Bc + (1.f - f) * z;
        A *= f;
    }
    const size_t ci = ((size_t)b * NC + chunk) * NH + h;
    g_carryA[ci] = A;
    g_carryB[ci] = Bc;
}

__global__ __launch_bounds__(256)
void fo_carry_scan_kernel() {
    const int idx = blockIdx.x * blockDim.x + threadIdx.x;
    const int h = idx & (NH - 1);
    const int b = idx >> 9;
    float c = 0.f;
#pragma unroll
    for (int j = 0; j < NC; j++) {
        const size_t ci = ((size_t)b * NC + j) * NH + h;
        g_cin[ci] = c;
        c = g_carryA[ci] * c + g_carryB[ci];
    }
}

__global__ __launch_bounds__(256)
void fo_apply_kernel(float* __restrict__ out) {
    const int idx   = blockIdx.x * blockDim.x + threadIdx.x;
    const int h     = idx & (NH - 1);
    const int chunk = (idx >> 9) & (NC - 1);
    const int b     = idx >> 12;

    const float* gp = g_gates + ((size_t)b * NT + (size_t)chunk * CT) * G3 + h;
    float* Cp  = out + ((size_t)b * NT + (size_t)chunk * CT) * NH + h;
    float* OCp = Cp + (size_t)NB * NT * NH;

    float c = g_cin[((size_t)b * NC + chunk) * NH + h];
#pragma unroll 4
    for (int t = 0; t < CT; t++) {
        const float* gt = gp + (size_t)t * G3;
        const float z = gt[0];
        const float f = gt[NH];
        const float o = gt[2 * NH];
        c = f * c + (1.f - f) * z;
        Cp[(size_t)t * NH]  = c;
        OCp[(size_t)t * NH] = o * c;
    }
}

// ---------------------------------------------------------------------------
extern "C" void kernel_launch(void* const* d_in, const int* in_sizes, int n_in,
                              void* d_out, int out_size) {
    const float* x    = (const float*)d_in[0];   // [B, T, D]
    const float* w    = (const float*)d_in[1];   // [3H, D, 2]
    const float* bias = (const float*)d_in[2];   // [3H]
    float* out = (float*)d_out;                  // C then O*C

    const int padN = NB * (NT + 1) * ND / 4;
    pad_x_kernel<<<(padN + 255) / 256, 256>>>((const float4*)x);
    transpose_wk_kernel<<<(KD * G3 + 255) / 256, 256>>>(w);

    cudaFuncSetAttribute(gemm_mma_kernel,
                         cudaFuncAttributeMaxDynamicSharedMemorySize, SMEM_TOTAL);
    dim3 grid(G3 / BN, (NB * NT) / BM);          // (12, 256)
    gemm_mma_kernel<<<grid, 256, SMEM_TOTAL>>>(bias);

    fo_carry_kernel<<<(NB * NC * NH) / 256, 256>>>();
    fo_carry_scan_kernel<<<(NB * NH) / 256, 256>>>();
    fo_apply_kernel<<<(NB * NC * NH) / 256, 256>>>(out);
}